// round 15
// baseline (speedup 1.0000x reference)
#include <cuda_runtime.h>
#include <cuda_bf16.h>
#include <cstdint>

// PairExcludeMask, fully fused single kernel:
//   out[f,i,n] = type_mask[ atype[f,i]*9 + tj ],
//   tj = (nlist==-1) ? 8 : atype[f, nlist]
//
// Each block packs 32 words of the global nibble table (8 types/u32), then
// arrives on a device counter. tid0 spins for all 512 arrivals (grid is
// co-resident by construction) and TMA-bulk-copies the 16KB frame table to
// smem. Meanwhile the block runs the pack-independent prologue: per-type row
// words, per-row center types, predicated nlist prefetch, and fast-path
// stores (rows that pass/fail every type need no table). Slow path after the
// mbarrier: LDS.32 nibble word -> (rw >> tj) & 1.
// Bounded spin + local-rebuild fallback guarantees forward progress even if
// co-residency breaks.

static constexpr int NF     = 4;
static constexpr int NLOC   = 16384;
static constexpr int NNEI   = 128;
static constexpr int NALL   = 32768;
static constexpr int NTYPES = 8;
static constexpr int TM1    = NTYPES + 1;          // 9
static constexpr uint32_t FULL = (1u << TM1) - 1;  // 0x1FF
static constexpr uint32_t ONEF = 0x3F800000u;      // 1.0f bits

static constexpr int WORDS     = NALL / 8;         // 4096 nibble words / frame
static constexpr int WORDS_P   = WORDS + 4;        // + virtual atom + pad
static constexpr int TBL_BYTES = WORDS_P * 4;      // 16400

static constexpr int THREADS_B = 512;
static constexpr int BPF       = 128;              // blocks per frame
static constexpr int ROWS_PB   = NLOC / BPF;       // 128 rows / block
static constexpr int ROW_VEC   = NNEI / 4;         // 32 vec4 per row
static constexpr int VEC_PB    = ROWS_PB * ROW_VEC;// 4096
static constexpr int ITERS     = VEC_PB / THREADS_B;   // 8
static constexpr int BLOCKS_B  = NF * BPF;         // 512
static constexpr int PACK_PW   = BLOCKS_B == 0 ? 0 : (NF * WORDS) / BLOCKS_B; // 32 words/block

static constexpr int SMEM_DYN  = TBL_BYTES;        // 16.4 KB

__device__ __align__(16) uint32_t g_nib[NF][WORDS_P];
__device__ uint32_t g_cnt;                          // monotonic arrival counter

__global__ __launch_bounds__(THREADS_B, 4)
void fused_kernel(const int4* __restrict__ nlist4,
                  const int*  __restrict__ atype,
                  const float* __restrict__ tmask,
                  uint4* __restrict__ out4)
{
    extern __shared__ __align__(16) uint32_t s_nib[];   // [WORDS_P]
    __shared__ __align__(8) unsigned long long s_mbar;
    __shared__ uint32_t s_rw[16];                        // per-type row word
    __shared__ int      s_ti[ROWS_PB];                   // per-row center type
    __shared__ uint32_t s_mode;                          // 1 = TMA, 0 = fallback

    const int tid  = threadIdx.x;
    const int bid  = blockIdx.x;
    const int f    = bid >> 7;                     // / BPF
    const int row0 = (bid & (BPF - 1)) * ROWS_PB;

    uint32_t mbar_addr;
    asm("{ .reg .u64 t; cvta.to.shared.u64 t, %1; cvt.u32.u64 %0, t; }"
        : "=r"(mbar_addr) : "l"(&s_mbar));
    uint32_t dst_addr;
    asm("{ .reg .u64 t; cvta.to.shared.u64 t, %1; cvt.u32.u64 %0, t; }"
        : "=r"(dst_addr) : "l"(s_nib));

    uint32_t spin_target = 0;

    // ---- 1. distributed pack: warp 0 packs this block's 32 words ----
    if (tid < PACK_PW) {
        const int word = bid * PACK_PW + tid;      // flat over NF*WORDS
        const int pf   = word >> 12;               // / WORDS (== f)
        const int wi   = word & (WORDS - 1);
        const int4* __restrict__ at4 = (const int4*)(atype + pf * NALL);
        int4 a = at4[wi * 2];
        int4 b = at4[wi * 2 + 1];
        uint32_t p = (uint32_t)a.x        | ((uint32_t)a.y << 4)
                   | ((uint32_t)a.z << 8) | ((uint32_t)a.w << 12)
                   | ((uint32_t)b.x << 16)| ((uint32_t)b.y << 20)
                   | ((uint32_t)b.z << 24)| ((uint32_t)b.w << 28);
        g_nib[pf][wi] = p;
        if (tid == 0 && (bid & (BPF - 1)) == 0) {  // frame's virtual-atom tail
            g_nib[f][WORDS]     = (uint32_t)NTYPES;
            g_nib[f][WORDS + 1] = 0;
            g_nib[f][WORDS + 2] = 0;
            g_nib[f][WORDS + 3] = 0;
        }
        __syncwarp();
        if (tid == 0) {
            __threadfence();                        // publish pack writes
            uint32_t old = atomicAdd(&g_cnt, 1u);
            spin_target = (old & ~511u) + 512u;     // replay-safe epoch end
        }
    }

    // ---- 2. pack-independent prologue tables ----
    if (tid >= 64 && tid < 64 + TM1) {             // 9 threads build s_rw
        const int ti = tid - 64;
        uint32_t w = 0;
        #pragma unroll
        for (int tj = 0; tj < TM1; ++tj)
            w |= (__ldg(tmask + ti * TM1 + tj) != 0.0f ? 1u : 0u) << tj;
        s_rw[ti] = w;
    }
    if (tid >= 128 && tid < 128 + ROWS_PB)         // 128 threads, 1 LDG each
        s_ti[tid - 128] = __ldg(atype + f * NALL + row0 + (tid - 128));
    if (tid == 40)
        asm volatile("mbarrier.init.shared.b64 [%0], 1;" :: "r"(mbar_addr) : "memory");

    __syncthreads();                               // tables + mbarrier visible

    // ---- 3. tid0: spin for global pack completion, then TMA ----
    if (tid == 0) {
        uint32_t c, mode = 1u;
        int polls = 0;
        do {
            asm volatile("ld.acquire.gpu.global.u32 %0, [%1];"
                         : "=r"(c) : "l"(&g_cnt) : "memory");
            if ((int32_t)(c - spin_target) >= 0) break;
            if (++polls > 8192) { mode = 0u; break; }   // fallback guard
        } while (true);
        s_mode = mode;
        if (mode) {
            asm volatile("fence.proxy.async.global;" ::: "memory");
            asm volatile("mbarrier.arrive.expect_tx.shared.b64 _, [%0], %1;"
                         :: "r"(mbar_addr), "r"((uint32_t)TBL_BYTES) : "memory");
            asm volatile("cp.async.bulk.shared::cluster.global.mbarrier::complete_tx::bytes "
                         "[%0], [%1], %2, [%3];"
                         :: "r"(dst_addr), "l"(g_nib[f]),
                            "r"((uint32_t)TBL_BYTES), "r"(mbar_addr) : "memory");
        }
    }

    const size_t base = ((size_t)f * NLOC + row0) * ROW_VEC;
    const int4*  __restrict__ nl = nlist4 + base;
    uint4*       __restrict__ ob = out4  + base;

    // ---- 4. prefetch nlist for first half (MLP=4), overlapping the TMA ----
    int4 nj[4];
    #pragma unroll
    for (int k = 0; k < 4; ++k) {
        const uint32_t rw = s_rw[s_ti[(tid + k * THREADS_B) >> 5]];
        if (rw != FULL && rw != 0u)
            nj[k] = nl[tid + k * THREADS_B];
    }

    // ---- 5. fast-path stores for ALL 8 items (no table needed) ----
    #pragma unroll
    for (int k = 0; k < ITERS; ++k) {
        const uint32_t rw = s_rw[s_ti[(tid + k * THREADS_B) >> 5]];
        if (rw == FULL)
            ob[tid + k * THREADS_B] = make_uint4(ONEF, ONEF, ONEF, ONEF);
        else if (rw == 0u)
            ob[tid + k * THREADS_B] = make_uint4(0u, 0u, 0u, 0u);
    }

    // ---- 6. table ready: mbarrier wait, or cooperative local rebuild ----
    __syncthreads();                               // s_mode visible to all
    if (s_mode) {
        uint32_t done;
        asm volatile(
            "{\n\t.reg .pred p;\n\t"
            "mbarrier.try_wait.parity.acquire.cta.shared::cta.b64 p, [%1], 0;\n\t"
            "selp.b32 %0, 1, 0, p;\n\t}"
            : "=r"(done) : "r"(mbar_addr) : "memory");
        while (!done) {
            asm volatile(
                "{\n\t.reg .pred p;\n\t"
                "mbarrier.try_wait.parity.acquire.cta.shared::cta.b64 p, [%1], 0, 0x989680;\n\t"
                "selp.b32 %0, 1, 0, p;\n\t}"
                : "=r"(done) : "r"(mbar_addr) : "memory");
        }
    } else {
        // fallback: build the frame's table locally (correct, slower)
        const int4* __restrict__ at4 = (const int4*)(atype + f * NALL);
        for (int wi = tid; wi < WORDS; wi += THREADS_B) {
            int4 a = at4[wi * 2];
            int4 b = at4[wi * 2 + 1];
            s_nib[wi] = (uint32_t)a.x        | ((uint32_t)a.y << 4)
                      | ((uint32_t)a.z << 8) | ((uint32_t)a.w << 12)
                      | ((uint32_t)b.x << 16)| ((uint32_t)b.y << 20)
                      | ((uint32_t)b.z << 24)| ((uint32_t)b.w << 28);
        }
        if (tid == 0) s_nib[WORDS] = (uint32_t)NTYPES;
        __syncthreads();
    }

    // ---- 7. slow path, first half (prefetched nj) ----
    #pragma unroll
    for (int k = 0; k < 4; ++k) {
        const uint32_t rw = s_rw[s_ti[(tid + k * THREADS_B) >> 5]];
        if (rw == FULL || rw == 0u) continue;
        const int v = tid + k * THREADS_B;

        uint32_t j0 = min((uint32_t)nj[k].x, (uint32_t)NALL);
        uint32_t j1 = min((uint32_t)nj[k].y, (uint32_t)NALL);
        uint32_t j2 = min((uint32_t)nj[k].z, (uint32_t)NALL);
        uint32_t j3 = min((uint32_t)nj[k].w, (uint32_t)NALL);

        uint32_t w0 = s_nib[j0 >> 3];
        uint32_t w1 = s_nib[j1 >> 3];
        uint32_t w2 = s_nib[j2 >> 3];
        uint32_t w3 = s_nib[j3 >> 3];

        uint32_t t0 = (w0 >> ((j0 & 7u) << 2)) & 15u;
        uint32_t t1 = (w1 >> ((j1 & 7u) << 2)) & 15u;
        uint32_t t2 = (w2 >> ((j2 & 7u) << 2)) & 15u;
        uint32_t t3 = (w3 >> ((j3 & 7u) << 2)) & 15u;

        uint4 r;
        r.x = ((rw >> t0) & 1u) ? ONEF : 0u;
        r.y = ((rw >> t1) & 1u) ? ONEF : 0u;
        r.z = ((rw >> t2) & 1u) ? ONEF : 0u;
        r.w = ((rw >> t3) & 1u) ? ONEF : 0u;

        ob[v] = r;
    }

    // ---- 8. slow path, second half: prefetch then consume ----
    #pragma unroll
    for (int k = 4; k < ITERS; ++k) {
        const uint32_t rw = s_rw[s_ti[(tid + k * THREADS_B) >> 5]];
        if (rw != FULL && rw != 0u)
            nj[k - 4] = nl[tid + k * THREADS_B];
    }
    #pragma unroll
    for (int k = 4; k < ITERS; ++k) {
        const uint32_t rw = s_rw[s_ti[(tid + k * THREADS_B) >> 5]];
        if (rw == FULL || rw == 0u) continue;
        const int v = tid + k * THREADS_B;

        uint32_t j0 = min((uint32_t)nj[k - 4].x, (uint32_t)NALL);
        uint32_t j1 = min((uint32_t)nj[k - 4].y, (uint32_t)NALL);
        uint32_t j2 = min((uint32_t)nj[k - 4].z, (uint32_t)NALL);
        uint32_t j3 = min((uint32_t)nj[k - 4].w, (uint32_t)NALL);

        uint32_t w0 = s_nib[j0 >> 3];
        uint32_t w1 = s_nib[j1 >> 3];
        uint32_t w2 = s_nib[j2 >> 3];
        uint32_t w3 = s_nib[j3 >> 3];

        uint32_t t0 = (w0 >> ((j0 & 7u) << 2)) & 15u;
        uint32_t t1 = (w1 >> ((j1 & 7u) << 2)) & 15u;
        uint32_t t2 = (w2 >> ((j2 & 7u) << 2)) & 15u;
        uint32_t t3 = (w3 >> ((j3 & 7u) << 2)) & 15u;

        uint4 r;
        r.x = ((rw >> t0) & 1u) ? ONEF : 0u;
        r.y = ((rw >> t1) & 1u) ? ONEF : 0u;
        r.z = ((rw >> t2) & 1u) ? ONEF : 0u;
        r.w = ((rw >> t3) & 1u) ? ONEF : 0u;

        ob[v] = r;
    }
}

extern "C" void kernel_launch(void* const* d_in, const int* in_sizes, int n_in,
                              void* d_out, int out_size)
{
    const int4*  nlist4 = (const int4*) d_in[0];
    const int*   atype  = (const int*)  d_in[1];
    const float* tmask  = (const float*)d_in[2];
    // d_in[3] = ntypes scalar (8, baked into constants)

    uint4* out4 = (uint4*)d_out;

    static bool configured = false;
    if (!configured) {
        cudaFuncSetAttribute(fused_kernel,
                             cudaFuncAttributeMaxDynamicSharedMemorySize,
                             SMEM_DYN);
        cudaFuncSetAttribute(fused_kernel,
                             cudaFuncAttributePreferredSharedMemoryCarveout,
                             100);
        configured = true;
    }

    fused_kernel<<<BLOCKS_B, THREADS_B, SMEM_DYN>>>(nlist4, atype, tmask, out4);
}

// round 16
// speedup vs baseline: 1.4800x; 1.4800x over previous
#include <cuda_runtime.h>
#include <cuda_bf16.h>
#include <cstdint>

// PairExcludeMask: out[f,i,n] = type_mask[ atype[f,i]*9 + tj ]
//   tj = (nlist[f,i,n] == -1) ? 8 : atype[f, nlist[f,i,n]]
//
// pack_kernel (primary): nibble table -- 8 atom types per u32, 16KB/frame.
// mask_kernel (secondary, PDL, 512 fat blocks of 8 items/thread): starts
// while pack runs. Pack-independent prologue: s_rw[9], s_ti[128], nlist
// prefetch for the first half, fast-path stores for ALL items. Only tid 0
// waits on the grid dependency and TMAs the table; the doubled per-block
// work amortizes that wait. Slow path: two halves with prefetch in between.

static constexpr int NF     = 4;
static constexpr int NLOC   = 16384;
static constexpr int NNEI   = 128;
static constexpr int NALL   = 32768;
static constexpr int NTYPES = 8;
static constexpr int TM1    = NTYPES + 1;          // 9
static constexpr uint32_t FULL = (1u << TM1) - 1;  // 0x1FF
static constexpr uint32_t ONEF = 0x3F800000u;      // 1.0f bits

static constexpr int WORDS     = NALL / 8;         // 4096 nibble words / frame
static constexpr int WORDS_P   = WORDS + 4;        // + virtual atom + pad
static constexpr int TBL_BYTES = WORDS_P * 4;      // 16400

__device__ __align__(16) uint32_t g_nib[NF][WORDS_P];

// ---------------- kernel 1 (primary): pack nibbles ----------------
static constexpr int PK_THREADS = 128;
static constexpr int PK_BLOCKS  = NF * WORDS / PK_THREADS;   // 128

__global__ __launch_bounds__(PK_THREADS)
void pack_kernel(const int* __restrict__ atype)
{
    const int idx = blockIdx.x * PK_THREADS + threadIdx.x;   // 0 .. NF*WORDS-1
    const int f  = idx >> 12;                         // / WORDS
    const int wi = idx & (WORDS - 1);
    const int4* __restrict__ at4 = (const int4*)(atype + f * NALL);
    int4 a = at4[wi * 2];
    int4 b = at4[wi * 2 + 1];
    uint32_t p = (uint32_t)a.x        | ((uint32_t)a.y << 4)
               | ((uint32_t)a.z << 8) | ((uint32_t)a.w << 12)
               | ((uint32_t)b.x << 16)| ((uint32_t)b.y << 20)
               | ((uint32_t)b.z << 24)| ((uint32_t)b.w << 28);
    g_nib[f][wi] = p;
    if (wi == 0) {                                    // virtual atom j == NALL
        g_nib[f][WORDS]     = (uint32_t)NTYPES;       // nibble 0 = type 8
        g_nib[f][WORDS + 1] = 0;
        g_nib[f][WORDS + 2] = 0;
        g_nib[f][WORDS + 3] = 0;
    }
}

// ---------------- kernel 2 (secondary, PDL): stream the mask ----------------
static constexpr int THREADS_B = 512;
static constexpr int BPF       = 128;                      // blocks per frame
static constexpr int ROWS_PB   = NLOC / BPF;               // 128 rows / block
static constexpr int ROW_VEC   = NNEI / 4;                 // 32 vec4 per row
static constexpr int VEC_PB    = ROWS_PB * ROW_VEC;        // 4096
static constexpr int ITERS     = VEC_PB / THREADS_B;       // 8
static constexpr int HALF      = ITERS / 2;                // 4
static constexpr int BLOCKS_B  = NF * BPF;                 // 512

static constexpr int SMEM_DYN  = TBL_BYTES;                // 16.4 KB

__global__ __launch_bounds__(THREADS_B)
void mask_kernel(const int4* __restrict__ nlist4,
                 const int*  __restrict__ atype,
                 const float* __restrict__ tmask,
                 uint4* __restrict__ out4)
{
    extern __shared__ __align__(16) uint32_t s_nib[];   // [WORDS_P]
    __shared__ __align__(8) unsigned long long s_mbar;
    __shared__ uint32_t s_rw[16];                        // per-type row word
    __shared__ int      s_ti[ROWS_PB];                   // per-row center type

    const int tid  = threadIdx.x;
    const int f    = blockIdx.x >> 7;              // / BPF
    const int row0 = (blockIdx.x & (BPF - 1)) * ROWS_PB;

    uint32_t mbar_addr;
    asm("{ .reg .u64 t; cvta.to.shared.u64 t, %1; cvt.u32.u64 %0, t; }"
        : "=r"(mbar_addr) : "l"(&s_mbar));
    uint32_t dst_addr;
    asm("{ .reg .u64 t; cvta.to.shared.u64 t, %1; cvt.u32.u64 %0, t; }"
        : "=r"(dst_addr) : "l"(s_nib));

    // ---- cheap, pack-independent prologue ----
    if (tid == 0)
        asm volatile("mbarrier.init.shared.b64 [%0], 1;" :: "r"(mbar_addr) : "memory");

    if (tid >= 32 && tid < 32 + TM1) {             // 9 threads build s_rw
        const int ti = tid - 32;
        uint32_t w = 0;
        #pragma unroll
        for (int tj = 0; tj < TM1; ++tj)
            w |= (__ldg(tmask + ti * TM1 + tj) != 0.0f ? 1u : 0u) << tj;
        s_rw[ti] = w;
    }
    if (tid >= 64 && tid < 64 + ROWS_PB)           // 128 threads, 1 LDG each
        s_ti[tid - 64] = __ldg(atype + f * NALL + row0 + (tid - 64));

    __syncthreads();                               // mbar + s_rw + s_ti visible

    // Only the TMA-issuing thread waits for pack's output.
    if (tid == 0) {
        cudaGridDependencySynchronize();
        asm volatile("mbarrier.arrive.expect_tx.shared.b64 _, [%0], %1;"
                     :: "r"(mbar_addr), "r"((uint32_t)TBL_BYTES) : "memory");
        asm volatile("cp.async.bulk.shared::cluster.global.mbarrier::complete_tx::bytes "
                     "[%0], [%1], %2, [%3];"
                     :: "r"(dst_addr), "l"(g_nib[f]),
                        "r"((uint32_t)TBL_BYTES), "r"(mbar_addr) : "memory");
    }

    const size_t base = ((size_t)f * NLOC + row0) * ROW_VEC;
    const int4*  __restrict__ nl = nlist4 + base;
    uint4*       __restrict__ ob = out4  + base;

    // ---- pack-independent bulk work (overlaps pack + the TMA copy) ----
    // prefetch nlist for the first half (MLP=4)
    int4 nj[HALF];
    #pragma unroll
    for (int k = 0; k < HALF; ++k) {
        const uint32_t rw = s_rw[s_ti[(tid + k * THREADS_B) >> 5]];
        if (rw != FULL && rw != 0u)
            nj[k] = nl[tid + k * THREADS_B];
    }
    // fast-path stores for ALL 8 items (no table needed)
    #pragma unroll
    for (int k = 0; k < ITERS; ++k) {
        const uint32_t rw = s_rw[s_ti[(tid + k * THREADS_B) >> 5]];
        if (rw == FULL)
            ob[tid + k * THREADS_B] = make_uint4(ONEF, ONEF, ONEF, ONEF);
        else if (rw == 0u)
            ob[tid + k * THREADS_B] = make_uint4(0u, 0u, 0u, 0u);
    }

    // ---- wait for the nibble table ----
    {
        uint32_t done;
        asm volatile(
            "{\n\t.reg .pred p;\n\t"
            "mbarrier.try_wait.parity.acquire.cta.shared::cta.b64 p, [%1], 0;\n\t"
            "selp.b32 %0, 1, 0, p;\n\t}"
            : "=r"(done) : "r"(mbar_addr) : "memory");
        while (!done) {
            asm volatile(
                "{\n\t.reg .pred p;\n\t"
                "mbarrier.try_wait.parity.acquire.cta.shared::cta.b64 p, [%1], 0, 0x989680;\n\t"
                "selp.b32 %0, 1, 0, p;\n\t}"
                : "=r"(done) : "r"(mbar_addr) : "memory");
        }
    }

    // ---- slow path, first half (prefetched) ----
    #pragma unroll
    for (int k = 0; k < HALF; ++k) {
        const uint32_t rw = s_rw[s_ti[(tid + k * THREADS_B) >> 5]];
        if (rw == FULL || rw == 0u) continue;
        const int v = tid + k * THREADS_B;

        uint32_t j0 = min((uint32_t)nj[k].x, (uint32_t)NALL);
        uint32_t j1 = min((uint32_t)nj[k].y, (uint32_t)NALL);
        uint32_t j2 = min((uint32_t)nj[k].z, (uint32_t)NALL);
        uint32_t j3 = min((uint32_t)nj[k].w, (uint32_t)NALL);

        uint32_t w0 = s_nib[j0 >> 3];
        uint32_t w1 = s_nib[j1 >> 3];
        uint32_t w2 = s_nib[j2 >> 3];
        uint32_t w3 = s_nib[j3 >> 3];

        uint32_t t0 = (w0 >> ((j0 & 7u) << 2)) & 15u;
        uint32_t t1 = (w1 >> ((j1 & 7u) << 2)) & 15u;
        uint32_t t2 = (w2 >> ((j2 & 7u) << 2)) & 15u;
        uint32_t t3 = (w3 >> ((j3 & 7u) << 2)) & 15u;

        uint4 r;
        r.x = ((rw >> t0) & 1u) ? ONEF : 0u;
        r.y = ((rw >> t1) & 1u) ? ONEF : 0u;
        r.z = ((rw >> t2) & 1u) ? ONEF : 0u;
        r.w = ((rw >> t3) & 1u) ? ONEF : 0u;

        ob[v] = r;
    }

    // ---- slow path, second half: prefetch then consume ----
    #pragma unroll
    for (int k = HALF; k < ITERS; ++k) {
        const uint32_t rw = s_rw[s_ti[(tid + k * THREADS_B) >> 5]];
        if (rw != FULL && rw != 0u)
            nj[k - HALF] = nl[tid + k * THREADS_B];
    }
    #pragma unroll
    for (int k = HALF; k < ITERS; ++k) {
        const uint32_t rw = s_rw[s_ti[(tid + k * THREADS_B) >> 5]];
        if (rw == FULL || rw == 0u) continue;
        const int v = tid + k * THREADS_B;

        uint32_t j0 = min((uint32_t)nj[k - HALF].x, (uint32_t)NALL);
        uint32_t j1 = min((uint32_t)nj[k - HALF].y, (uint32_t)NALL);
        uint32_t j2 = min((uint32_t)nj[k - HALF].z, (uint32_t)NALL);
        uint32_t j3 = min((uint32_t)nj[k - HALF].w, (uint32_t)NALL);

        uint32_t w0 = s_nib[j0 >> 3];
        uint32_t w1 = s_nib[j1 >> 3];
        uint32_t w2 = s_nib[j2 >> 3];
        uint32_t w3 = s_nib[j3 >> 3];

        uint32_t t0 = (w0 >> ((j0 & 7u) << 2)) & 15u;
        uint32_t t1 = (w1 >> ((j1 & 7u) << 2)) & 15u;
        uint32_t t2 = (w2 >> ((j2 & 7u) << 2)) & 15u;
        uint32_t t3 = (w3 >> ((j3 & 7u) << 2)) & 15u;

        uint4 r;
        r.x = ((rw >> t0) & 1u) ? ONEF : 0u;
        r.y = ((rw >> t1) & 1u) ? ONEF : 0u;
        r.z = ((rw >> t2) & 1u) ? ONEF : 0u;
        r.w = ((rw >> t3) & 1u) ? ONEF : 0u;

        ob[v] = r;
    }
}

extern "C" void kernel_launch(void* const* d_in, const int* in_sizes, int n_in,
                              void* d_out, int out_size)
{
    const int4*  nlist4 = (const int4*) d_in[0];
    const int*   atype  = (const int*)  d_in[1];
    const float* tmask  = (const float*)d_in[2];
    // d_in[3] = ntypes scalar (8, baked into constants)

    uint4* out4 = (uint4*)d_out;

    static bool configured = false;
    if (!configured) {
        cudaFuncSetAttribute(mask_kernel,
                             cudaFuncAttributeMaxDynamicSharedMemorySize,
                             SMEM_DYN);
        cudaFuncSetAttribute(mask_kernel,
                             cudaFuncAttributePreferredSharedMemoryCarveout,
                             100);
        configured = true;
    }

    pack_kernel<<<PK_BLOCKS, PK_THREADS>>>(atype);

    // PDL: mask_kernel starts while pack_kernel is still running; only the
    // TMA-issuing thread of each block waits on the grid dependency.
    cudaLaunchConfig_t cfg = {};
    cfg.gridDim  = dim3(BLOCKS_B, 1, 1);
    cfg.blockDim = dim3(THREADS_B, 1, 1);
    cfg.dynamicSmemBytes = SMEM_DYN;
    cfg.stream = 0;
    cudaLaunchAttribute attr[1];
    attr[0].id = cudaLaunchAttributeProgrammaticStreamSerialization;
    attr[0].val.programmaticStreamSerializationAllowed = 1;
    cfg.attrs = attr;
    cfg.numAttrs = 1;
    cudaLaunchKernelEx(&cfg, mask_kernel, nlist4, atype, tmask, out4);
}

// round 17
// speedup vs baseline: 1.4837x; 1.0025x over previous
#include <cuda_runtime.h>
#include <cuda_bf16.h>
#include <cstdint>

// PairExcludeMask: out[f,i,n] = type_mask[ atype[f,i]*9 + tj ]
//   tj = (nlist[f,i,n] == -1) ? 8 : atype[f, nlist[f,i,n]]
//
// pack_kernel (primary): per atom j a BYTE whose bit ti = (type_mask[ti*9+tj]!=0)
// -- the slow path needs no second lookup: mask = (B[j] >> ti) & 1.
// mask_kernel (secondary, PDL, 512 fat blocks x 8 items/thread): starts while
// pack runs. Pack-independent prologue: s_rw[9] + s_ti[128], nlist prefetch
// (first half), fast-path stores for ALL items (rows passing/failing every
// type). Only tid 0 waits on the grid dependency and TMAs the byte table.
// Slow path: LDS.U8; (B & (1<<ti)) ? 1.0f : 0.0f, two halves with prefetch.

static constexpr int NF     = 4;
static constexpr int NLOC   = 16384;
static constexpr int NNEI   = 128;
static constexpr int NALL   = 32768;
static constexpr int NTYPES = 8;
static constexpr int TM1    = NTYPES + 1;          // 9
static constexpr uint32_t FULL = (1u << TM1) - 1;  // 0x1FF
static constexpr uint32_t ONEF = 0x3F800000u;      // 1.0f bits

static constexpr int TBL_BYTES = NALL + 16;        // 32784 (16B multiple)

__device__ __align__(16) uint8_t g_byte[NF][TBL_BYTES];

// ---------------- kernel 1 (primary): per-atom mask byte ----------------
static constexpr int PK_THREADS = 256;
static constexpr int PK_BLOCKS  = NF * NALL / 16 / PK_THREADS;   // 32

__global__ __launch_bounds__(PK_THREADS)
void pack_kernel(const int* __restrict__ atype, const float* __restrict__ tmask)
{
    __shared__ uint32_t s_tb[16];                  // per-neighbor-type byte
    if (threadIdx.x < TM1) {
        uint32_t b = 0;
        #pragma unroll
        for (int ti = 0; ti < NTYPES; ++ti)        // centers have ti < 8
            b |= (tmask[ti * TM1 + threadIdx.x] != 0.0f ? 1u : 0u) << ti;
        s_tb[threadIdx.x] = b;
    }
    __syncthreads();

    const int idx = blockIdx.x * PK_THREADS + threadIdx.x;  // over NF*NALL/16
    const int f   = idx >> 11;                        // / (NALL/16)
    const int wi  = idx & (NALL / 16 - 1);
    const int4* __restrict__ at4 = (const int4*)(atype + f * NALL);

    uint4 o;
    uint32_t* po = &o.x;
    #pragma unroll
    for (int q = 0; q < 4; ++q) {
        int4 a = at4[wi * 4 + q];
        po[q] = s_tb[a.x] | (s_tb[a.y] << 8) | (s_tb[a.z] << 16) | (s_tb[a.w] << 24);
    }
    ((uint4*)g_byte[f])[wi] = o;

    if (wi == 0) {                                 // virtual atom j == NALL
        uint32_t v = s_tb[NTYPES];
        #pragma unroll
        for (int k = 0; k < 16; ++k)
            g_byte[f][NALL + k] = (uint8_t)(k == 0 ? v : 0);
    }
}

// ---------------- kernel 2 (secondary, PDL): stream the mask ----------------
static constexpr int THREADS_B = 512;
static constexpr int BPF       = 128;                      // blocks per frame
static constexpr int ROWS_PB   = NLOC / BPF;               // 128 rows / block
static constexpr int ROW_VEC   = NNEI / 4;                 // 32 vec4 per row
static constexpr int VEC_PB    = ROWS_PB * ROW_VEC;        // 4096
static constexpr int ITERS     = VEC_PB / THREADS_B;       // 8
static constexpr int HALF      = ITERS / 2;                // 4
static constexpr int BLOCKS_B  = NF * BPF;                 // 512

static constexpr int SMEM_DYN  = TBL_BYTES;                // 32.8 KB

__global__ __launch_bounds__(THREADS_B)
void mask_kernel(const int4* __restrict__ nlist4,
                 const int*  __restrict__ atype,
                 const float* __restrict__ tmask,
                 uint4* __restrict__ out4)
{
    extern __shared__ __align__(16) uint8_t s_byte[];    // [TBL_BYTES]
    __shared__ __align__(8) unsigned long long s_mbar;
    __shared__ uint32_t s_rw[16];                        // per-type row word
    __shared__ int      s_ti[ROWS_PB];                   // per-row center type

    const int tid  = threadIdx.x;
    const int f    = blockIdx.x >> 7;              // / BPF
    const int row0 = (blockIdx.x & (BPF - 1)) * ROWS_PB;

    uint32_t mbar_addr;
    asm("{ .reg .u64 t; cvta.to.shared.u64 t, %1; cvt.u32.u64 %0, t; }"
        : "=r"(mbar_addr) : "l"(&s_mbar));
    uint32_t dst_addr;
    asm("{ .reg .u64 t; cvta.to.shared.u64 t, %1; cvt.u32.u64 %0, t; }"
        : "=r"(dst_addr) : "l"(s_byte));

    // ---- cheap, pack-independent prologue ----
    if (tid == 0)
        asm volatile("mbarrier.init.shared.b64 [%0], 1;" :: "r"(mbar_addr) : "memory");

    if (tid >= 32 && tid < 32 + TM1) {             // 9 threads build s_rw
        const int ti = tid - 32;
        uint32_t w = 0;
        #pragma unroll
        for (int tj = 0; tj < TM1; ++tj)
            w |= (__ldg(tmask + ti * TM1 + tj) != 0.0f ? 1u : 0u) << tj;
        s_rw[ti] = w;
    }
    if (tid >= 64 && tid < 64 + ROWS_PB)           // 128 threads, 1 LDG each
        s_ti[tid - 64] = __ldg(atype + f * NALL + row0 + (tid - 64));

    __syncthreads();                               // mbar + s_rw + s_ti visible

    // Only the TMA-issuing thread waits for pack's output.
    if (tid == 0) {
        cudaGridDependencySynchronize();
        asm volatile("mbarrier.arrive.expect_tx.shared.b64 _, [%0], %1;"
                     :: "r"(mbar_addr), "r"((uint32_t)TBL_BYTES) : "memory");
        asm volatile("cp.async.bulk.shared::cluster.global.mbarrier::complete_tx::bytes "
                     "[%0], [%1], %2, [%3];"
                     :: "r"(dst_addr), "l"(g_byte[f]),
                        "r"((uint32_t)TBL_BYTES), "r"(mbar_addr) : "memory");
    }

    const size_t base = ((size_t)f * NLOC + row0) * ROW_VEC;
    const int4*  __restrict__ nl = nlist4 + base;
    uint4*       __restrict__ ob = out4  + base;

    // ---- pack-independent bulk work (overlaps pack + the TMA copy) ----
    int4 nj[HALF];
    #pragma unroll
    for (int k = 0; k < HALF; ++k) {
        const uint32_t rw = s_rw[s_ti[(tid + k * THREADS_B) >> 5]];
        if (rw != FULL && rw != 0u)
            nj[k] = nl[tid + k * THREADS_B];
    }
    #pragma unroll
    for (int k = 0; k < ITERS; ++k) {
        const uint32_t rw = s_rw[s_ti[(tid + k * THREADS_B) >> 5]];
        if (rw == FULL)
            ob[tid + k * THREADS_B] = make_uint4(ONEF, ONEF, ONEF, ONEF);
        else if (rw == 0u)
            ob[tid + k * THREADS_B] = make_uint4(0u, 0u, 0u, 0u);
    }

    // ---- wait for the byte table ----
    {
        uint32_t done;
        asm volatile(
            "{\n\t.reg .pred p;\n\t"
            "mbarrier.try_wait.parity.acquire.cta.shared::cta.b64 p, [%1], 0;\n\t"
            "selp.b32 %0, 1, 0, p;\n\t}"
            : "=r"(done) : "r"(mbar_addr) : "memory");
        while (!done) {
            asm volatile(
                "{\n\t.reg .pred p;\n\t"
                "mbarrier.try_wait.parity.acquire.cta.shared::cta.b64 p, [%1], 0, 0x989680;\n\t"
                "selp.b32 %0, 1, 0, p;\n\t}"
                : "=r"(done) : "r"(mbar_addr) : "memory");
        }
    }

    // ---- slow path, first half (prefetched) ----
    #pragma unroll
    for (int k = 0; k < HALF; ++k) {
        const int row = (tid + k * THREADS_B) >> 5;
        const int ti  = s_ti[row];
        const uint32_t rw = s_rw[ti];
        if (rw == FULL || rw == 0u) continue;
        const int v = tid + k * THREADS_B;
        const uint32_t m = 1u << ti;               // warp-uniform

        uint32_t j0 = min((uint32_t)nj[k].x, (uint32_t)NALL);
        uint32_t j1 = min((uint32_t)nj[k].y, (uint32_t)NALL);
        uint32_t j2 = min((uint32_t)nj[k].z, (uint32_t)NALL);
        uint32_t j3 = min((uint32_t)nj[k].w, (uint32_t)NALL);

        uint32_t b0 = s_byte[j0];
        uint32_t b1 = s_byte[j1];
        uint32_t b2 = s_byte[j2];
        uint32_t b3 = s_byte[j3];

        uint4 r;
        r.x = (b0 & m) ? ONEF : 0u;
        r.y = (b1 & m) ? ONEF : 0u;
        r.z = (b2 & m) ? ONEF : 0u;
        r.w = (b3 & m) ? ONEF : 0u;

        ob[v] = r;
    }

    // ---- slow path, second half: prefetch then consume ----
    #pragma unroll
    for (int k = HALF; k < ITERS; ++k) {
        const uint32_t rw = s_rw[s_ti[(tid + k * THREADS_B) >> 5]];
        if (rw != FULL && rw != 0u)
            nj[k - HALF] = nl[tid + k * THREADS_B];
    }
    #pragma unroll
    for (int k = HALF; k < ITERS; ++k) {
        const int row = (tid + k * THREADS_B) >> 5;
        const int ti  = s_ti[row];
        const uint32_t rw = s_rw[ti];
        if (rw == FULL || rw == 0u) continue;
        const int v = tid + k * THREADS_B;
        const uint32_t m = 1u << ti;

        uint32_t j0 = min((uint32_t)nj[k - HALF].x, (uint32_t)NALL);
        uint32_t j1 = min((uint32_t)nj[k - HALF].y, (uint32_t)NALL);
        uint32_t j2 = min((uint32_t)nj[k - HALF].z, (uint32_t)NALL);
        uint32_t j3 = min((uint32_t)nj[k - HALF].w, (uint32_t)NALL);

        uint32_t b0 = s_byte[j0];
        uint32_t b1 = s_byte[j1];
        uint32_t b2 = s_byte[j2];
        uint32_t b3 = s_byte[j3];

        uint4 r;
        r.x = (b0 & m) ? ONEF : 0u;
        r.y = (b1 & m) ? ONEF : 0u;
        r.z = (b2 & m) ? ONEF : 0u;
        r.w = (b3 & m) ? ONEF : 0u;

        ob[v] = r;
    }
}

extern "C" void kernel_launch(void* const* d_in, const int* in_sizes, int n_in,
                              void* d_out, int out_size)
{
    const int4*  nlist4 = (const int4*) d_in[0];
    const int*   atype  = (const int*)  d_in[1];
    const float* tmask  = (const float*)d_in[2];
    // d_in[3] = ntypes scalar (8, baked into constants)

    uint4* out4 = (uint4*)d_out;

    static bool configured = false;
    if (!configured) {
        cudaFuncSetAttribute(mask_kernel,
                             cudaFuncAttributeMaxDynamicSharedMemorySize,
                             SMEM_DYN);
        cudaFuncSetAttribute(mask_kernel,
                             cudaFuncAttributePreferredSharedMemoryCarveout,
                             100);
        configured = true;
    }

    pack_kernel<<<PK_BLOCKS, PK_THREADS>>>(atype, tmask);

    // PDL: mask_kernel starts while pack_kernel is still running; only the
    // TMA-issuing thread of each block waits on the grid dependency.
    cudaLaunchConfig_t cfg = {};
    cfg.gridDim  = dim3(BLOCKS_B, 1, 1);
    cfg.blockDim = dim3(THREADS_B, 1, 1);
    cfg.dynamicSmemBytes = SMEM_DYN;
    cfg.stream = 0;
    cudaLaunchAttribute attr[1];
    attr[0].id = cudaLaunchAttributeProgrammaticStreamSerialization;
    attr[0].val.programmaticStreamSerializationAllowed = 1;
    cfg.attrs = attr;
    cfg.numAttrs = 1;
    cudaLaunchKernelEx(&cfg, mask_kernel, nlist4, atype, tmask, out4);
}